// round 1
// baseline (speedup 1.0000x reference)
#include <cuda_runtime.h>
#include <math.h>

#define B_ 16
#define T_ 128
#define S_ 128
#define E_ 512
#define H_ 512
#define V_ 4096

#define LSTM_BLOCKS 128
#define LSTM_SMEM 70656  // (16*128 + 128*18) float4 + 256 floats

// ---------------- scratch (device globals; no cudaMalloc allowed) -------------
__device__ float g_x[2048 * 512];        // embedded input [B*T, E]
__device__ float g_gates[2048 * 2048];   // precomputed input gates [B*T, 4H]
__device__ float g_y1[2048 * 512];       // layer0 outputs
__device__ float g_cat[2048 * 1024];     // [y2 | context]  [B*T, H+E]
__device__ float g_encf[2048 * 512];     // enc_feat [B*S, H]
__device__ float g_decf[2048 * 512];     // dec_feat [B*T, H]
__device__ float g_ench[16 * 512];       // enc_hidden (mean of memory)
__device__ float g_h0[16 * 512];         // h double buffer A
__device__ float g_h1[16 * 512];         // h double buffer B
__device__ unsigned long long g_bar_cnt; // zero-initialized, monotone

// ---------------- grid barrier (persistent kernel) ----------------------------
__device__ __forceinline__ void grid_barrier() {
    __syncthreads();
    if (threadIdx.x == 0) {
        __threadfence();
        unsigned long long old = atomicAdd(&g_bar_cnt, 1ULL);
        unsigned long long target = (old / LSTM_BLOCKS + 1ULL) * LSTM_BLOCKS;
        while (*((volatile unsigned long long*)&g_bar_cnt) < target) { }
        __threadfence();
    }
    __syncthreads();
}

// ---------------- embedding gather --------------------------------------------
__global__ void k_embed(const int* __restrict__ tgt, const float* __restrict__ emb,
                        float* __restrict__ x) {
    int r = blockIdx.x;                 // b*T + t
    int tok = tgt[r];
    ((float4*)x)[r * 128 + threadIdx.x] = ((const float4*)emb)[tok * 128 + threadIdx.x];
}

// ---------------- mean over source positions ----------------------------------
__global__ void k_mean(const float* __restrict__ mem, float* __restrict__ out) {
    int b = blockIdx.x;
    int e = threadIdx.x;                // 512 threads
    float s = 0.f;
    for (int t = 0; t < S_; t++) s += mem[(b * S_ + t) * 512 + e];
    out[b * 512 + e] = s * (1.f / (float)S_);
}

// ---------------- generic SGEMM: C[M,N] = A[M,K] @ W[N,K]^T + b1 + b2 ---------
__global__ __launch_bounds__(256, 2) void sgemm_bias(
    const float* __restrict__ A, int lda,
    const float* __restrict__ W, int K,
    const float* __restrict__ bias1, const float* __restrict__ bias2,
    float* __restrict__ C, int ldc) {
    __shared__ float As[8][132];
    __shared__ float Bs[8][132];
    const int tid = threadIdx.x;
    const int m0 = blockIdx.y * 128;
    const int n0 = blockIdx.x * 128;
    const int tx = tid & 15;
    const int ty = tid >> 4;
    const int lr = tid >> 1;            // 0..127
    const int lk = (tid & 1) * 4;       // 0 or 4
    const float* Ap = A + (size_t)(m0 + lr) * lda + lk;
    const float* Wp = W + (size_t)(n0 + lr) * K + lk;

    float acc[8][8];
#pragma unroll
    for (int i = 0; i < 8; i++)
#pragma unroll
        for (int j = 0; j < 8; j++) acc[i][j] = 0.f;

    for (int k0 = 0; k0 < K; k0 += 8) {
        float4 av = *(const float4*)(Ap + k0);
        float4 bv = *(const float4*)(Wp + k0);
        __syncthreads();
        As[lk + 0][lr] = av.x; As[lk + 1][lr] = av.y;
        As[lk + 2][lr] = av.z; As[lk + 3][lr] = av.w;
        Bs[lk + 0][lr] = bv.x; Bs[lk + 1][lr] = bv.y;
        Bs[lk + 2][lr] = bv.z; Bs[lk + 3][lr] = bv.w;
        __syncthreads();
#pragma unroll
        for (int kk = 0; kk < 8; kk++) {
            float a[8], b[8];
            *(float4*)(a)     = *(const float4*)(&As[kk][ty * 8]);
            *(float4*)(a + 4) = *(const float4*)(&As[kk][ty * 8 + 4]);
            *(float4*)(b)     = *(const float4*)(&Bs[kk][tx * 8]);
            *(float4*)(b + 4) = *(const float4*)(&Bs[kk][tx * 8 + 4]);
#pragma unroll
            for (int i = 0; i < 8; i++)
#pragma unroll
                for (int j = 0; j < 8; j++)
                    acc[i][j] = fmaf(a[i], b[j], acc[i][j]);
        }
    }

    float bsv[8];
#pragma unroll
    for (int j = 0; j < 8; j++) {
        int n = n0 + tx * 8 + j;
        float bb = bias1 ? bias1[n] : 0.f;
        if (bias2) bb += bias2[n];
        bsv[j] = bb;
    }
#pragma unroll
    for (int i = 0; i < 8; i++) {
        int row = m0 + ty * 8 + i;
        float4 o0, o1;
        o0.x = acc[i][0] + bsv[0]; o0.y = acc[i][1] + bsv[1];
        o0.z = acc[i][2] + bsv[2]; o0.w = acc[i][3] + bsv[3];
        o1.x = acc[i][4] + bsv[4]; o1.y = acc[i][5] + bsv[5];
        o1.z = acc[i][6] + bsv[6]; o1.w = acc[i][7] + bsv[7];
        *(float4*)&C[(size_t)row * ldc + n0 + tx * 8]     = o0;
        *(float4*)&C[(size_t)row * ldc + n0 + tx * 8 + 4] = o1;
    }
}

// ---------------- persistent LSTM layer ---------------------------------------
// Block bidx owns h indices [bidx*4, bidx*4+4) for all 16 batches, all 4 gates.
// W_hh rows stay in SMEM for all 128 steps. h double-buffered in global.
__global__ __launch_bounds__(256, 1) void k_lstm(
    const float* __restrict__ gates_pre,  // [B*T, 2048]
    const float* __restrict__ Whh,        // [2048, 512]
    const float* __restrict__ h_init,     // [B, 512]
    float* __restrict__ ybase, int ystride,
    float* __restrict__ hfin, float* __restrict__ cfin,
    float* __restrict__ hb0, float* __restrict__ hb1) {
    extern __shared__ float4 sm4[];
    float4* Ws4 = sm4;                  // [16][128]
    float4* Hs4 = sm4 + 16 * 128;       // [128][18] (padded)
    float* gsm  = (float*)(sm4 + 16 * 128 + 128 * 18);  // [16][16]

    const int tid = threadIdx.x;
    const int bidx = blockIdx.x;
    const int b  = tid & 15;
    const int nl = tid >> 4;            // 0..15  (gate*4 + h_local)
    const int gate = nl >> 2;
    const int hl = nl & 3;
    const int h_idx = bidx * 4 + hl;
    const int n_global = gate * 512 + h_idx;

    // stage W_hh rows for this block (persist across all steps)
    for (int idx = tid; idx < 16 * 128; idx += 256) {
        int r = idx >> 7, k4 = idx & 127;
        int ng = (r >> 2) * 512 + bidx * 4 + (r & 3);
        Ws4[r * 128 + k4] = ((const float4*)Whh)[ng * 128 + k4];
    }
    // init h buffer slice + c registers
    float c_reg = 0.f;
    const int cb = tid & 15, chl = tid >> 4;  // cell-thread identity (tid<64)
    const int ch = bidx * 4 + chl;
    if (tid < 64) hb0[cb * 512 + ch] = h_init[cb * 512 + ch];
    grid_barrier();

    for (int t = 0; t < T_; t++) {
        const float* hin = (t & 1) ? hb1 : hb0;
        float* hout      = (t & 1) ? hb0 : hb1;
        // stage h  (bypass L1: written by other SMs last step)
#pragma unroll
        for (int i = 0; i < 8; i++) {
            int g = tid + 256 * i;      // 0..2047 = b*128 + k4
            int gb = g >> 7, gk4 = g & 127;
            Hs4[gk4 * 18 + gb] = __ldcg(((const float4*)hin) + g);
        }
        __syncthreads();

        float acc = gates_pre[((size_t)(b * T_ + t)) * 2048 + n_global];
        const float4* wr = Ws4 + nl * 128;
        float s = 0.f;
#pragma unroll 16
        for (int k4 = 0; k4 < 128; k4++) {
            float4 w  = wr[k4];
            float4 hv = Hs4[k4 * 18 + b];
            s = fmaf(w.x, hv.x, s);
            s = fmaf(w.y, hv.y, s);
            s = fmaf(w.z, hv.z, s);
            s = fmaf(w.w, hv.w, s);
        }
        acc += s;
        gsm[nl * 16 + b] = acc;
        __syncthreads();

        if (tid < 64) {
            float gi = gsm[(0 * 4 + chl) * 16 + cb];
            float gf = gsm[(1 * 4 + chl) * 16 + cb];
            float gg = gsm[(2 * 4 + chl) * 16 + cb];
            float go = gsm[(3 * 4 + chl) * 16 + cb];
            float iv = 1.f / (1.f + expf(-gi));
            float fv = 1.f / (1.f + expf(-gf));
            float gv = tanhf(gg);
            float ov = 1.f / (1.f + expf(-go));
            c_reg = fv * c_reg + iv * gv;
            float hv = ov * tanhf(c_reg);
            hout[cb * 512 + ch] = hv;
            ybase[((size_t)(cb * T_ + t)) * ystride + ch] = hv;
            if (t == T_ - 1) {
                hfin[cb * 512 + ch] = hv;
                cfin[cb * 512 + ch] = c_reg;
            }
        }
        grid_barrier();
    }
}

// ---------------- fused attention: energy + softmax + context -----------------
// Block = (b, tile of 8 t). Streams enc_feat / memory rows through SMEM.
__global__ __launch_bounds__(256) void k_attn(
    const float* __restrict__ encf, const float* __restrict__ decf,
    const float* __restrict__ mem, const unsigned char* __restrict__ mask,
    const float* __restrict__ v, const float* __restrict__ vb,
    float* __restrict__ outcat) {
    __shared__ float df[8][512];
    __shared__ float vsh[512];
    __shared__ float row[512];
    __shared__ float en[8][128];
    const int b = blockIdx.x;
    const int t0 = blockIdx.y * 8;
    const int tid = threadIdx.x;
    const int w = tid >> 5, lane = tid & 31;

    for (int i = tid; i < 512; i += 256) vsh[i] = v[i];
    for (int i = tid; i < 8 * 512; i += 256) {
        int j = i >> 9, h = i & 511;
        df[j][h] = decf[((size_t)(b * T_ + t0 + j)) * 512 + h];
    }
    __syncthreads();
    const float vbv = vb[0];

    // phase 1: energies
    for (int s = 0; s < S_; s++) {
        for (int i = tid; i < 512; i += 256) row[i] = encf[((size_t)(b * S_ + s)) * 512 + i];
        __syncthreads();
        float e = 0.f;
#pragma unroll
        for (int i = 0; i < 16; i++) {
            int h = lane + 32 * i;
            e = fmaf(vsh[h], tanhf(row[h] + df[w][h]), e);
        }
#pragma unroll
        for (int off = 16; off; off >>= 1) e += __shfl_xor_sync(0xffffffffu, e, off);
        if (lane == 0) {
            e += vbv;
            if (mask[b * S_ + s]) e = -1e9f;
            en[w][s] = e;
        }
        __syncthreads();
    }

    // softmax (warp w handles t0+w)
    {
        float vals[4];
        float m = -1e30f;
#pragma unroll
        for (int i = 0; i < 4; i++) { vals[i] = en[w][lane + 32 * i]; m = fmaxf(m, vals[i]); }
#pragma unroll
        for (int off = 16; off; off >>= 1) m = fmaxf(m, __shfl_xor_sync(0xffffffffu, m, off));
        float ssum = 0.f;
#pragma unroll
        for (int i = 0; i < 4; i++) { vals[i] = expf(vals[i] - m); ssum += vals[i]; }
#pragma unroll
        for (int off = 16; off; off >>= 1) ssum += __shfl_xor_sync(0xffffffffu, ssum, off);
        float inv = 1.f / ssum;
#pragma unroll
        for (int i = 0; i < 4; i++) en[w][lane + 32 * i] = vals[i] * inv;
    }
    __syncthreads();

    // phase 2: context = attn @ memory
    float c0[8], c1[8];
#pragma unroll
    for (int j = 0; j < 8; j++) { c0[j] = 0.f; c1[j] = 0.f; }
    for (int s = 0; s < S_; s++) {
        for (int i = tid; i < 512; i += 256) row[i] = mem[((size_t)(b * S_ + s)) * 512 + i];
        __syncthreads();
        float m0 = row[tid], m1 = row[tid + 256];
#pragma unroll
        for (int j = 0; j < 8; j++) {
            float a = en[j][s];
            c0[j] = fmaf(a, m0, c0[j]);
            c1[j] = fmaf(a, m1, c1[j]);
        }
        __syncthreads();
    }
#pragma unroll
    for (int j = 0; j < 8; j++) {
        size_t r = ((size_t)(b * T_ + t0 + j)) * 1024 + 512;
        outcat[r + tid] = c0[j];
        outcat[r + tid + 256] = c1[j];
    }
}

// ---------------- launch -------------------------------------------------------
extern "C" void kernel_launch(void* const* d_in, const int* in_sizes, int n_in,
                              void* d_out, int out_size) {
    (void)in_sizes; (void)n_in; (void)out_size;
    const int*   tgt  = (const int*)d_in[0];
    const float* mem  = (const float*)d_in[1];
    const unsigned char* mask = (const unsigned char*)d_in[2];
    const float* emb  = (const float*)d_in[3];
    const float* Wih0 = (const float*)d_in[4];
    const float* Whh0 = (const float*)d_in[5];
    const float* bih0 = (const float*)d_in[6];
    const float* bhh0 = (const float*)d_in[7];
    const float* Wih1 = (const float*)d_in[8];
    const float* Whh1 = (const float*)d_in[9];
    const float* bih1 = (const float*)d_in[10];
    const float* bhh1 = (const float*)d_in[11];
    const float* Wh   = (const float*)d_in[12];
    const float* bh   = (const float*)d_in[13];
    const float* Ws   = (const float*)d_in[14];
    const float* bs   = (const float*)d_in[15];
    const float* v    = (const float*)d_in[16];
    const float* vb   = (const float*)d_in[17];
    const float* Wout = (const float*)d_in[18];
    const float* bout = (const float*)d_in[19];

    float* out = (float*)d_out;
    float* logits = out;                            // [B,T,V] = 8388608
    float* hn = out + (size_t)B_ * T_ * V_;         // [2,B,H] = 16384
    float* cn = hn + 2 * B_ * H_;                   // [2,B,H] = 16384

    float *px, *pgates, *py1, *pcat, *pencf, *pdecf, *pench, *ph0, *ph1;
    cudaGetSymbolAddress((void**)&px, g_x);
    cudaGetSymbolAddress((void**)&pgates, g_gates);
    cudaGetSymbolAddress((void**)&py1, g_y1);
    cudaGetSymbolAddress((void**)&pcat, g_cat);
    cudaGetSymbolAddress((void**)&pencf, g_encf);
    cudaGetSymbolAddress((void**)&pdecf, g_decf);
    cudaGetSymbolAddress((void**)&pench, g_ench);
    cudaGetSymbolAddress((void**)&ph0, g_h0);
    cudaGetSymbolAddress((void**)&ph1, g_h1);

    cudaFuncSetAttribute(k_lstm, cudaFuncAttributeMaxDynamicSharedMemorySize, LSTM_SMEM);

    // 1. embedding + enc_hidden
    k_embed<<<2048, 128>>>(tgt, emb, px);
    k_mean<<<B_, 512>>>(mem, pench);

    // 2. layer0 input gates, layer0 recurrence
    sgemm_bias<<<dim3(16, 16), 256>>>(px, 512, Wih0, 512, bih0, bhh0, pgates, 2048);
    k_lstm<<<LSTM_BLOCKS, 256, LSTM_SMEM>>>(pgates, Whh0, pench, py1, 512,
                                            hn, cn, ph0, ph1);

    // 3. layer1 input gates, layer1 recurrence (y2 -> first half of g_cat)
    sgemm_bias<<<dim3(16, 16), 256>>>(py1, 512, Wih1, 512, bih1, bhh1, pgates, 2048);
    k_lstm<<<LSTM_BLOCKS, 256, LSTM_SMEM>>>(pgates, Whh1, pench, pcat, 1024,
                                            hn + B_ * H_, cn + B_ * H_, ph0, ph1);

    // 4. attention features
    sgemm_bias<<<dim3(4, 16), 256>>>(mem, 512, Wh, 512, bh, nullptr, pencf, 512);
    sgemm_bias<<<dim3(4, 16), 256>>>(pcat, 1024, Ws, 512, bs, nullptr, pdecf, 512);

    // 5. fused energy/softmax/context -> second half of g_cat
    k_attn<<<dim3(B_, T_ / 8), 256>>>(pencf, pdecf, mem, mask, v, vb, pcat);

    // 6. output projection
    sgemm_bias<<<dim3(32, 16), 256>>>(pcat, 1024, Wout, 1024, bout, nullptr, logits, 4096);
}

// round 2
// speedup vs baseline: 1.1516x; 1.1516x over previous
#include <cuda_runtime.h>
#include <math.h>

#define B_ 16
#define T_ 128
#define S_ 128
#define E_ 512
#define H_ 512
#define V_ 4096

#define LSTM_BLOCKS 128
#define LSTM_THREADS 512
// smem: h (512*16 f) + partials (16*16*20 f) + gsm (256 f)
#define LSTM_SMEM (32768 + 20480 + 1024)

// ---------------- scratch (device globals; no cudaMalloc allowed) -------------
__device__ float g_x[2048 * 512];        // embedded input [B*T, E]
__device__ float g_gates[2048 * 2048];   // precomputed input gates [B*T, 4H]
__device__ float g_y1[2048 * 512];       // layer0 outputs
__device__ float g_cat[2048 * 1024];     // [y2 | context]  [B*T, H+E]
__device__ float g_encf[2048 * 512];     // enc_feat [B*S, H]
__device__ float g_decf[2048 * 512];     // dec_feat [B*T, H]
__device__ float g_ench_t[512 * 16];     // enc_hidden TRANSPOSED [H][B]
__device__ float g_h0[512 * 16];         // h double buffer A  [k][b]
__device__ float g_h1[512 * 16];         // h double buffer B  [k][b]
__device__ unsigned long long g_bar_cnt; // zero-initialized, monotone

// ---------------- fast activations ---------------------------------------------
__device__ __forceinline__ float fsig(float x)  { return 1.f / (1.f + __expf(-x)); }
__device__ __forceinline__ float ftanh(float x) { return 1.f - 2.f / (__expf(2.f * x) + 1.f); }

// ---------------- grid barrier (persistent kernel) ----------------------------
__device__ __forceinline__ void grid_barrier() {
    __threadfence();
    __syncthreads();
    if (threadIdx.x == 0) {
        unsigned long long old = atomicAdd(&g_bar_cnt, 1ULL);
        unsigned long long target = (old / LSTM_BLOCKS + 1ULL) * LSTM_BLOCKS;
        while (*((volatile unsigned long long*)&g_bar_cnt) < target) { }
        __threadfence();
    }
    __syncthreads();
}

// ---------------- embedding gather --------------------------------------------
__global__ void k_embed(const int* __restrict__ tgt, const float* __restrict__ emb,
                        float* __restrict__ x) {
    int r = blockIdx.x;
    int tok = tgt[r];
    ((float4*)x)[r * 128 + threadIdx.x] = ((const float4*)emb)[tok * 128 + threadIdx.x];
}

// ---------------- mean over source positions (writes TRANSPOSED [e][b]) -------
__global__ void k_mean(const float* __restrict__ mem, float* __restrict__ out_t) {
    int b = blockIdx.x;
    int e = threadIdx.x;                // 512 threads
    float s = 0.f;
    for (int t = 0; t < S_; t++) s += mem[(b * S_ + t) * 512 + e];
    out_t[e * 16 + b] = s * (1.f / (float)S_);
}

// ---------------- generic SGEMM: C[M,N] = A[M,K] @ W[N,K]^T + b1 + b2 ---------
__global__ __launch_bounds__(256, 2) void sgemm_bias(
    const float* __restrict__ A, int lda,
    const float* __restrict__ W, int K,
    const float* __restrict__ bias1, const float* __restrict__ bias2,
    float* __restrict__ C, int ldc) {
    __shared__ float As[8][132];
    __shared__ float Bs[8][132];
    const int tid = threadIdx.x;
    const int m0 = blockIdx.y * 128;
    const int n0 = blockIdx.x * 128;
    const int tx = tid & 15;
    const int ty = tid >> 4;
    const int lr = tid >> 1;
    const int lk = (tid & 1) * 4;
    const float* Ap = A + (size_t)(m0 + lr) * lda + lk;
    const float* Wp = W + (size_t)(n0 + lr) * K + lk;

    float acc[8][8];
#pragma unroll
    for (int i = 0; i < 8; i++)
#pragma unroll
        for (int j = 0; j < 8; j++) acc[i][j] = 0.f;

    for (int k0 = 0; k0 < K; k0 += 8) {
        float4 av = *(const float4*)(Ap + k0);
        float4 bv = *(const float4*)(Wp + k0);
        __syncthreads();
        As[lk + 0][lr] = av.x; As[lk + 1][lr] = av.y;
        As[lk + 2][lr] = av.z; As[lk + 3][lr] = av.w;
        Bs[lk + 0][lr] = bv.x; Bs[lk + 1][lr] = bv.y;
        Bs[lk + 2][lr] = bv.z; Bs[lk + 3][lr] = bv.w;
        __syncthreads();
#pragma unroll
        for (int kk = 0; kk < 8; kk++) {
            float a[8], b[8];
            *(float4*)(a)     = *(const float4*)(&As[kk][ty * 8]);
            *(float4*)(a + 4) = *(const float4*)(&As[kk][ty * 8 + 4]);
            *(float4*)(b)     = *(const float4*)(&Bs[kk][tx * 8]);
            *(float4*)(b + 4) = *(const float4*)(&Bs[kk][tx * 8 + 4]);
#pragma unroll
            for (int i = 0; i < 8; i++)
#pragma unroll
                for (int j = 0; j < 8; j++)
                    acc[i][j] = fmaf(a[i], b[j], acc[i][j]);
        }
    }

    float bsv[8];
#pragma unroll
    for (int j = 0; j < 8; j++) {
        int n = n0 + tx * 8 + j;
        float bb = bias1 ? bias1[n] : 0.f;
        if (bias2) bb += bias2[n];
        bsv[j] = bb;
    }
#pragma unroll
    for (int i = 0; i < 8; i++) {
        int row = m0 + ty * 8 + i;
        float4 o0, o1;
        o0.x = acc[i][0] + bsv[0]; o0.y = acc[i][1] + bsv[1];
        o0.z = acc[i][2] + bsv[2]; o0.w = acc[i][3] + bsv[3];
        o1.x = acc[i][4] + bsv[4]; o1.y = acc[i][5] + bsv[5];
        o1.z = acc[i][6] + bsv[6]; o1.w = acc[i][7] + bsv[7];
        *(float4*)&C[(size_t)row * ldc + n0 + tx * 8]     = o0;
        *(float4*)&C[(size_t)row * ldc + n0 + tx * 8 + 4] = o1;
    }
}

// ---------------- persistent LSTM layer (weights in registers) -----------------
// 128 CTAs x 512 threads. CTA owns 16 gate-rows: nl in [0,16), gate=nl>>2,
// h_idx = bidx*4 + (nl&3). Thread = (bg in 4 batches, rg in 8 row-pairs,
// ks in 16 k-slices of 32). Weights (2 rows x 32 k) live in registers for the
// whole kernel. h exchanged via global in transposed [k][b] layout.
__global__ __launch_bounds__(LSTM_THREADS, 1) void k_lstm(
    const float* __restrict__ gates_pre,  // [B*T, 2048]
    const float* __restrict__ Whh,        // [2048, 512]
    const float* __restrict__ h_init_t,   // [512][16] transposed
    float* __restrict__ ybase, int ystride,
    float* __restrict__ hfin, float* __restrict__ cfin,
    float* __restrict__ hb0, float* __restrict__ hb1) {
    extern __shared__ float smf[];
    float4* h_sm4 = (float4*)smf;                 // [512*4] float4 = 32KB
    float*  pr    = smf + 512 * 16;               // [16 ks][16 nl][20] floats
    float4* pr4   = (float4*)pr;
    float*  gsm   = pr + 16 * 16 * 20;            // [16 nl][16 b]

    const int tid = threadIdx.x;
    const int bidx = blockIdx.x;
    const int bg = tid & 3;          // batch group (4 batches each)
    const int rg = (tid >> 2) & 7;   // row pair
    const int ks = tid >> 5;         // k slice (32 k)
    const int k0 = ks * 32;

    // ---- load weights into registers (constant across all timesteps) ----
    float4 w4[2][8];
#pragma unroll
    for (int ri = 0; ri < 2; ri++) {
        int nl = 2 * rg + ri;
        int ng = (nl >> 2) * 512 + bidx * 4 + (nl & 3);
#pragma unroll
        for (int c = 0; c < 8; c++)
            w4[ri][c] = ((const float4*)Whh)[ng * 128 + ks * 8 + c];
    }

    // cell-update thread identity (tid < 64)
    float c_reg = 0.f;
    const int cb = tid & 15, chl = (tid >> 4) & 3;
    const int ch = bidx * 4 + chl;

    grid_barrier();   // align generations with other launches

    for (int t = 0; t < T_; t++) {
        const float* hin = (t == 0) ? h_init_t : ((t & 1) ? hb1 : hb0);
        float* hout      = (t & 1) ? hb0 : hb1;

        // stage h [k][b] -> smem (straight float4 copy, L1-bypass)
#pragma unroll
        for (int i = 0; i < 4; i++) {
            int g = tid + LSTM_THREADS * i;
            h_sm4[g] = __ldcg(((const float4*)hin) + g);
        }
        __syncthreads();

        // partial dot products: 2 rows x 4 batches x 32 k
        float4 acc0 = make_float4(0.f, 0.f, 0.f, 0.f);
        float4 acc1 = make_float4(0.f, 0.f, 0.f, 0.f);
#pragma unroll
        for (int c = 0; c < 8; c++) {
            float4 wa = w4[0][c];
            float4 wb = w4[1][c];
            const float* wav = (const float*)&wa;
            const float* wbv = (const float*)&wb;
#pragma unroll
            for (int j = 0; j < 4; j++) {
                float4 hv = h_sm4[(k0 + c * 4 + j) * 4 + bg];
                float a = wav[j], b = wbv[j];
                acc0.x = fmaf(a, hv.x, acc0.x); acc0.y = fmaf(a, hv.y, acc0.y);
                acc0.z = fmaf(a, hv.z, acc0.z); acc0.w = fmaf(a, hv.w, acc0.w);
                acc1.x = fmaf(b, hv.x, acc1.x); acc1.y = fmaf(b, hv.y, acc1.y);
                acc1.z = fmaf(b, hv.z, acc1.z); acc1.w = fmaf(b, hv.w, acc1.w);
            }
        }
        {
            int nl0 = 2 * rg;
            pr4[ks * 80 + nl0 * 5 + bg]       = acc0;
            pr4[ks * 80 + (nl0 + 1) * 5 + bg] = acc1;
        }
        __syncthreads();

        // reduce over 16 k-slices, add precomputed input gates
        if (tid < 256) {
            int nl = tid >> 4, b = tid & 15;
            float s = 0.f;
#pragma unroll
            for (int kq = 0; kq < 16; kq++)
                s += pr[kq * 320 + nl * 20 + b];
            int ng = (nl >> 2) * 512 + bidx * 4 + (nl & 3);
            s += gates_pre[((size_t)(b * T_ + t)) * 2048 + ng];
            gsm[nl * 16 + b] = s;
        }
        __syncthreads();

        // cell update
        if (tid < 64) {
            float gi = gsm[(0 * 4 + chl) * 16 + cb];
            float gf = gsm[(1 * 4 + chl) * 16 + cb];
            float gg = gsm[(2 * 4 + chl) * 16 + cb];
            float go = gsm[(3 * 4 + chl) * 16 + cb];
            float iv = fsig(gi);
            float fv = fsig(gf);
            float gv = ftanh(gg);
            float ov = fsig(go);
            c_reg = fv * c_reg + iv * gv;
            float hv = ov * ftanh(c_reg);
            hout[ch * 16 + cb] = hv;                                  // [k][b]
            ybase[((size_t)(cb * T_ + t)) * ystride + ch] = hv;       // [b][t][H]
            if (t == T_ - 1) {
                hfin[cb * 512 + ch] = hv;
                cfin[cb * 512 + ch] = c_reg;
            }
        }
        grid_barrier();
    }
}

// ---------------- fused attention: energy + softmax + context -----------------
__global__ __launch_bounds__(256) void k_attn(
    const float* __restrict__ encf, const float* __restrict__ decf,
    const float* __restrict__ mem, const unsigned char* __restrict__ mask,
    const float* __restrict__ v, const float* __restrict__ vb,
    float* __restrict__ outcat) {
    __shared__ float df[8][512];
    __shared__ float vsh[512];
    __shared__ float row[512];
    __shared__ float en[8][128];
    const int b = blockIdx.x;
    const int t0 = blockIdx.y * 8;
    const int tid = threadIdx.x;
    const int w = tid >> 5, lane = tid & 31;

    for (int i = tid; i < 512; i += 256) vsh[i] = v[i];
    for (int i = tid; i < 8 * 512; i += 256) {
        int j = i >> 9, h = i & 511;
        df[j][h] = decf[((size_t)(b * T_ + t0 + j)) * 512 + h];
    }
    __syncthreads();
    const float vbv = vb[0];

    for (int s = 0; s < S_; s++) {
        for (int i = tid; i < 512; i += 256) row[i] = encf[((size_t)(b * S_ + s)) * 512 + i];
        __syncthreads();
        float e = 0.f;
#pragma unroll
        for (int i = 0; i < 16; i++) {
            int h = lane + 32 * i;
            e = fmaf(vsh[h], ftanh(row[h] + df[w][h]), e);
        }
#pragma unroll
        for (int off = 16; off; off >>= 1) e += __shfl_xor_sync(0xffffffffu, e, off);
        if (lane == 0) {
            e += vbv;
            if (mask[b * S_ + s]) e = -1e9f;
            en[w][s] = e;
        }
        __syncthreads();
    }

    {
        float vals[4];
        float m = -1e30f;
#pragma unroll
        for (int i = 0; i < 4; i++) { vals[i] = en[w][lane + 32 * i]; m = fmaxf(m, vals[i]); }
#pragma unroll
        for (int off = 16; off; off >>= 1) m = fmaxf(m, __shfl_xor_sync(0xffffffffu, m, off));
        float ssum = 0.f;
#pragma unroll
        for (int i = 0; i < 4; i++) { vals[i] = __expf(vals[i] - m); ssum += vals[i]; }
#pragma unroll
        for (int off = 16; off; off >>= 1) ssum += __shfl_xor_sync(0xffffffffu, ssum, off);
        float inv = 1.f / ssum;
#pragma unroll
        for (int i = 0; i < 4; i++) en[w][lane + 32 * i] = vals[i] * inv;
    }
    __syncthreads();

    float c0[8], c1[8];
#pragma unroll
    for (int j = 0; j < 8; j++) { c0[j] = 0.f; c1[j] = 0.f; }
    for (int s = 0; s < S_; s++) {
        for (int i = tid; i < 512; i += 256) row[i] = mem[((size_t)(b * S_ + s)) * 512 + i];
        __syncthreads();
        float m0 = row[tid], m1 = row[tid + 256];
#pragma unroll
        for (int j = 0; j < 8; j++) {
            float a = en[j][s];
            c0[j] = fmaf(a, m0, c0[j]);
            c1[j] = fmaf(a, m1, c1[j]);
        }
        __syncthreads();
    }
#pragma unroll
    for (int j = 0; j < 8; j++) {
        size_t r = ((size_t)(b * T_ + t0 + j)) * 1024 + 512;
        outcat[r + tid] = c0[j];
        outcat[r + tid + 256] = c1[j];
    }
}

// ---------------- launch -------------------------------------------------------
extern "C" void kernel_launch(void* const* d_in, const int* in_sizes, int n_in,
                              void* d_out, int out_size) {
    (void)in_sizes; (void)n_in; (void)out_size;
    const int*   tgt  = (const int*)d_in[0];
    const float* mem  = (const float*)d_in[1];
    const unsigned char* mask = (const unsigned char*)d_in[2];
    const float* emb  = (const float*)d_in[3];
    const float* Wih0 = (const float*)d_in[4];
    const float* Whh0 = (const float*)d_in[5];
    const float* bih0 = (const float*)d_in[6];
    const float* bhh0 = (const float*)d_in[7];
    const float* Wih1 = (const float*)d_in[8];
    const float* Whh1 = (const float*)d_in[9];
    const float* bih1 = (const float*)d_in[10];
    const float* bhh1 = (const float*)d_in[11];
    const float* Wh   = (const float*)d_in[12];
    const float* bh   = (const float*)d_in[13];
    const float* Ws   = (const float*)d_in[14];
    const float* bs   = (const float*)d_in[15];
    const float* v    = (const float*)d_in[16];
    const float* vb   = (const float*)d_in[17];
    const float* Wout = (const float*)d_in[18];
    const float* bout = (const float*)d_in[19];

    float* out = (float*)d_out;
    float* logits = out;
    float* hn = out + (size_t)B_ * T_ * V_;
    float* cn = hn + 2 * B_ * H_;

    float *px, *pgates, *py1, *pcat, *pencf, *pdecf, *pench, *ph0, *ph1;
    cudaGetSymbolAddress((void**)&px, g_x);
    cudaGetSymbolAddress((void**)&pgates, g_gates);
    cudaGetSymbolAddress((void**)&py1, g_y1);
    cudaGetSymbolAddress((void**)&pcat, g_cat);
    cudaGetSymbolAddress((void**)&pencf, g_encf);
    cudaGetSymbolAddress((void**)&pdecf, g_decf);
    cudaGetSymbolAddress((void**)&pench, g_ench_t);
    cudaGetSymbolAddress((void**)&ph0, g_h0);
    cudaGetSymbolAddress((void**)&ph1, g_h1);

    cudaFuncSetAttribute(k_lstm, cudaFuncAttributeMaxDynamicSharedMemorySize, LSTM_SMEM);

    // 1. embedding + enc_hidden (transposed)
    k_embed<<<2048, 128>>>(tgt, emb, px);
    k_mean<<<B_, 512>>>(mem, pench);

    // 2. layer0 input gates, layer0 recurrence
    sgemm_bias<<<dim3(16, 16), 256>>>(px, 512, Wih0, 512, bih0, bhh0, pgates, 2048);
    k_lstm<<<LSTM_BLOCKS, LSTM_THREADS, LSTM_SMEM>>>(pgates, Whh0, pench, py1, 512,
                                                     hn, cn, ph0, ph1);

    // 3. layer1 input gates, layer1 recurrence (y2 -> first half of g_cat)
    sgemm_bias<<<dim3(16, 16), 256>>>(py1, 512, Wih1, 512, bih1, bhh1, pgates, 2048);
    k_lstm<<<LSTM_BLOCKS, LSTM_THREADS, LSTM_SMEM>>>(pgates, Whh1, pench, pcat, 1024,
                                                     hn + B_ * H_, cn + B_ * H_, ph0, ph1);

    // 4. attention features
    sgemm_bias<<<dim3(4, 16), 256>>>(mem, 512, Wh, 512, bh, nullptr, pencf, 512);
    sgemm_bias<<<dim3(4, 16), 256>>>(pcat, 1024, Ws, 512, bs, nullptr, pdecf, 512);

    // 5. fused energy/softmax/context -> second half of g_cat
    k_attn<<<dim3(B_, T_ / 8), 256>>>(pencf, pdecf, mem, mask, v, vb, pcat);

    // 6. output projection
    sgemm_bias<<<dim3(32, 16), 256>>>(pcat, 1024, Wout, 1024, bout, nullptr, logits, 4096);
}

// round 3
// speedup vs baseline: 1.5427x; 1.3396x over previous
#include <cuda_runtime.h>
#include <math.h>
#include <stdint.h>

#define B_ 16
#define T_ 128
#define S_ 128
#define E_ 512
#define H_ 512
#define V_ 4096

#define LSTM_BLOCKS 128
#define LSTM_THREADS 512
// smem: h (512*16 f) + partials (16*16*20 f) + gsm (256 f)
#define LSTM_SMEM (32768 + 20480 + 1024)

// ---------------- scratch (device globals; no cudaMalloc allowed) -------------
__device__ float g_x[2048 * 512];        // embedded input [B*T, E]
__device__ float g_gates[2048 * 2048];   // precomputed input gates [B*T, 4H]
__device__ float g_y1[2048 * 512];       // layer0 outputs
__device__ float g_cat[2048 * 1024];     // [y2 | context]  [B*T, H+E]
__device__ float g_encf[2048 * 512];     // enc_feat [B*S, H]
__device__ float g_decf[2048 * 512];     // dec_feat [B*T, H]
__device__ float g_ench_t[512 * 16];     // enc_hidden TRANSPOSED [H][B]
__device__ float g_h0[512 * 16];         // h double buffer A  [k][b]
__device__ float g_h1[512 * 16];         // h double buffer B  [k][b]
__device__ unsigned long long g_bar_cnt; // zero-initialized, monotone

// ---------------- fast activations ---------------------------------------------
__device__ __forceinline__ float fsig(float x)  { return 1.f / (1.f + __expf(-x)); }
__device__ __forceinline__ float ftanh(float x) { return 1.f - 2.f / (__expf(2.f * x) + 1.f); }

// ---------------- grid barrier (persistent kernel) ----------------------------
__device__ __forceinline__ void grid_barrier() {
    __threadfence();
    __syncthreads();
    if (threadIdx.x == 0) {
        unsigned long long old = atomicAdd(&g_bar_cnt, 1ULL);
        unsigned long long target = (old / LSTM_BLOCKS + 1ULL) * LSTM_BLOCKS;
        while (*((volatile unsigned long long*)&g_bar_cnt) < target) { __nanosleep(32); }
        __threadfence();
    }
    __syncthreads();
}

// ---------------- embedding gather --------------------------------------------
__global__ void k_embed(const int* __restrict__ tgt, const float* __restrict__ emb,
                        float* __restrict__ x) {
    int r = blockIdx.x;
    int tok = tgt[r];
    ((float4*)x)[r * 128 + threadIdx.x] = ((const float4*)emb)[tok * 128 + threadIdx.x];
}

// ---------------- mean over source positions (writes TRANSPOSED [e][b]) -------
__global__ void k_mean(const float* __restrict__ mem, float* __restrict__ out_t) {
    int b = blockIdx.x;
    int e = threadIdx.x;                // 512 threads
    float s = 0.f;
    for (int t = 0; t < S_; t++) s += mem[(b * S_ + t) * 512 + e];
    out_t[e * 16 + b] = s * (1.f / (float)S_);
}

// ---------------- tf32 tensor-core GEMM ----------------------------------------
// C[M,N] = A[M,K] @ W[N,K]^T + bias1 (+bias2). 128x128 tile, 8 warps (2m x 4n),
// each warp 64x32 via m16n8k8 tf32 mma. Smem row stride 20 -> conflict-free frags.
__device__ __forceinline__ uint32_t f2tf32(float f) {
    uint32_t u; asm("cvt.rna.tf32.f32 %0, %1;" : "=r"(u) : "f"(f)); return u;
}
__device__ __forceinline__ void mma_tf32(float* d, const uint32_t* a, const uint32_t* b) {
    asm volatile("mma.sync.aligned.m16n8k8.row.col.f32.tf32.tf32.f32 "
        "{%0,%1,%2,%3}, {%4,%5,%6,%7}, {%8,%9}, {%0,%1,%2,%3};"
        : "+f"(d[0]), "+f"(d[1]), "+f"(d[2]), "+f"(d[3])
        : "r"(a[0]), "r"(a[1]), "r"(a[2]), "r"(a[3]), "r"(b[0]), "r"(b[1]));
}
__device__ __forceinline__ void sts_cvt4(float* dst, float4 v) {
    uint4 u;
    u.x = f2tf32(v.x); u.y = f2tf32(v.y); u.z = f2tf32(v.z); u.w = f2tf32(v.w);
    *(uint4*)dst = u;
}

__global__ __launch_bounds__(256, 2) void gemm_tf32(
    const float* __restrict__ A, int lda,
    const float* __restrict__ W, int ldw, int K,
    const float* __restrict__ bias1, const float* __restrict__ bias2,
    float* __restrict__ C, int ldc) {
    __shared__ float As[128 * 20];
    __shared__ float Bs[128 * 20];
    const int tid = threadIdx.x;
    const int m0 = blockIdx.y * 128, n0 = blockIdx.x * 128;
    const int warp = tid >> 5, lane = tid & 31;
    const int wm = (warp & 1) * 64;
    const int wn = (warp >> 1) * 32;
    const int g = lane >> 2, c = lane & 3;

    const int lr = tid >> 2;       // 0..63
    const int lq = tid & 3;        // float4 slot within k16
    const float* Ap = A + (size_t)(m0 + lr) * lda + lq * 4;
    const float* Wp = W + (size_t)(n0 + lr) * ldw + lq * 4;
    const size_t astep = (size_t)64 * lda;
    const size_t wstep = (size_t)64 * ldw;

    float4 ar0 = *(const float4*)(Ap);
    float4 ar1 = *(const float4*)(Ap + astep);
    float4 br0 = *(const float4*)(Wp);
    float4 br1 = *(const float4*)(Wp + wstep);

    float acc[4][4][4];
#pragma unroll
    for (int i = 0; i < 4; i++)
#pragma unroll
        for (int j = 0; j < 4; j++)
#pragma unroll
            for (int q = 0; q < 4; q++) acc[i][j][q] = 0.f;

    const int nkt = K >> 4;
    for (int kt = 0; kt < nkt; kt++) {
        __syncthreads();
        sts_cvt4(&As[lr * 20 + lq * 4], ar0);
        sts_cvt4(&As[(lr + 64) * 20 + lq * 4], ar1);
        sts_cvt4(&Bs[lr * 20 + lq * 4], br0);
        sts_cvt4(&Bs[(lr + 64) * 20 + lq * 4], br1);
        __syncthreads();
        if (kt + 1 < nkt) {
            const float* Ap2 = Ap + (kt + 1) * 16;
            const float* Wp2 = Wp + (kt + 1) * 16;
            ar0 = *(const float4*)(Ap2);
            ar1 = *(const float4*)(Ap2 + astep);
            br0 = *(const float4*)(Wp2);
            br1 = *(const float4*)(Wp2 + wstep);
        }
#pragma unroll
        for (int kk = 0; kk < 16; kk += 8) {
            uint32_t af[4][4];
            uint32_t bf[4][2];
#pragma unroll
            for (int mt = 0; mt < 4; mt++) {
                int mr = wm + mt * 16 + g;
                af[mt][0] = __float_as_uint(As[mr * 20 + kk + c]);
                af[mt][1] = __float_as_uint(As[(mr + 8) * 20 + kk + c]);
                af[mt][2] = __float_as_uint(As[mr * 20 + kk + c + 4]);
                af[mt][3] = __float_as_uint(As[(mr + 8) * 20 + kk + c + 4]);
            }
#pragma unroll
            for (int nt = 0; nt < 4; nt++) {
                int nr = wn + nt * 8 + g;
                bf[nt][0] = __float_as_uint(Bs[nr * 20 + kk + c]);
                bf[nt][1] = __float_as_uint(Bs[nr * 20 + kk + c + 4]);
            }
#pragma unroll
            for (int mt = 0; mt < 4; mt++)
#pragma unroll
                for (int nt = 0; nt < 4; nt++)
                    mma_tf32(acc[mt][nt], af[mt], bf[nt]);
        }
    }

    // epilogue
    float bv0[4], bv1[4];
#pragma unroll
    for (int nt = 0; nt < 4; nt++) {
        int col = n0 + wn + nt * 8 + 2 * c;
        float x0 = bias1 ? __ldg(&bias1[col]) : 0.f;
        float x1 = bias1 ? __ldg(&bias1[col + 1]) : 0.f;
        if (bias2) { x0 += __ldg(&bias2[col]); x1 += __ldg(&bias2[col + 1]); }
        bv0[nt] = x0; bv1[nt] = x1;
    }
#pragma unroll
    for (int mt = 0; mt < 4; mt++) {
        int r0 = m0 + wm + mt * 16 + g;
#pragma unroll
        for (int nt = 0; nt < 4; nt++) {
            int col = n0 + wn + nt * 8 + 2 * c;
            float2 o0 = make_float2(acc[mt][nt][0] + bv0[nt], acc[mt][nt][1] + bv1[nt]);
            float2 o1 = make_float2(acc[mt][nt][2] + bv0[nt], acc[mt][nt][3] + bv1[nt]);
            *(float2*)&C[(size_t)r0 * ldc + col] = o0;
            *(float2*)&C[(size_t)(r0 + 8) * ldc + col] = o1;
        }
    }
}

// ---------------- persistent LSTM layer (weights in registers) -----------------
__global__ __launch_bounds__(LSTM_THREADS, 1) void k_lstm(
    const float* __restrict__ gates_pre,  // [B*T, 2048]
    const float* __restrict__ Whh,        // [2048, 512]
    const float* __restrict__ h_init_t,   // [512][16] transposed
    float* __restrict__ ybase, int ystride,
    float* __restrict__ hfin, float* __restrict__ cfin,
    float* __restrict__ hb0, float* __restrict__ hb1) {
    extern __shared__ float smf[];
    float4* h_sm4 = (float4*)smf;                 // [512*4] float4 = 32KB
    float*  pr    = smf + 512 * 16;               // [16 ks][16 nl][20] floats
    float4* pr4   = (float4*)pr;
    float*  gsm   = pr + 16 * 16 * 20;            // [16 nl][16 b]

    const int tid = threadIdx.x;
    const int bidx = blockIdx.x;
    const int bg = tid & 3;
    const int rg = (tid >> 2) & 7;
    const int ks = tid >> 5;
    const int k0 = ks * 32;

    // weights in registers (constant across all timesteps)
    float4 w4[2][8];
#pragma unroll
    for (int ri = 0; ri < 2; ri++) {
        int nl = 2 * rg + ri;
        int ng = (nl >> 2) * 512 + bidx * 4 + (nl & 3);
#pragma unroll
        for (int c = 0; c < 8; c++)
            w4[ri][c] = ((const float4*)Whh)[ng * 128 + ks * 8 + c];
    }

    // reduce-thread identity + gates prefetch register
    const int r_nl = tid >> 4, r_b = tid & 15;     // valid for tid<256
    const int r_ng = (r_nl >> 2) * 512 + bidx * 4 + (r_nl & 3);
    float gpre = 0.f;
    if (tid < 256) gpre = gates_pre[((size_t)(r_b * T_)) * 2048 + r_ng];

    // cell-update thread identity (tid < 64)
    float c_reg = 0.f;
    const int cb = tid & 15, chl = (tid >> 4) & 3;
    const int ch = bidx * 4 + chl;

    grid_barrier();

    for (int t = 0; t < T_; t++) {
        const float* hin = (t == 0) ? h_init_t : ((t & 1) ? hb1 : hb0);
        float* hout      = (t & 1) ? hb0 : hb1;

#pragma unroll
        for (int i = 0; i < 4; i++) {
            int g = tid + LSTM_THREADS * i;
            h_sm4[g] = __ldcg(((const float4*)hin) + g);
        }
        __syncthreads();

        float4 acc0 = make_float4(0.f, 0.f, 0.f, 0.f);
        float4 acc1 = make_float4(0.f, 0.f, 0.f, 0.f);
#pragma unroll
        for (int c = 0; c < 8; c++) {
            float4 wa = w4[0][c];
            float4 wb = w4[1][c];
            const float* wav = (const float*)&wa;
            const float* wbv = (const float*)&wb;
#pragma unroll
            for (int j = 0; j < 4; j++) {
                float4 hv = h_sm4[(k0 + c * 4 + j) * 4 + bg];
                float a = wav[j], b = wbv[j];
                acc0.x = fmaf(a, hv.x, acc0.x); acc0.y = fmaf(a, hv.y, acc0.y);
                acc0.z = fmaf(a, hv.z, acc0.z); acc0.w = fmaf(a, hv.w, acc0.w);
                acc1.x = fmaf(b, hv.x, acc1.x); acc1.y = fmaf(b, hv.y, acc1.y);
                acc1.z = fmaf(b, hv.z, acc1.z); acc1.w = fmaf(b, hv.w, acc1.w);
            }
        }
        {
            int nl0 = 2 * rg;
            pr4[ks * 80 + nl0 * 5 + bg]       = acc0;
            pr4[ks * 80 + (nl0 + 1) * 5 + bg] = acc1;
        }
        __syncthreads();

        if (tid < 256) {
            float s = gpre;
#pragma unroll
            for (int kq = 0; kq < 16; kq++)
                s += pr[kq * 320 + r_nl * 20 + r_b];
            gsm[r_nl * 16 + r_b] = s;
            // prefetch gates for next step (latency hidden by cell+barrier+stage)
            if (t + 1 < T_)
                gpre = gates_pre[((size_t)(r_b * T_ + t + 1)) * 2048 + r_ng];
        }
        __syncthreads();

        if (tid < 64) {
            float gi = gsm[(0 * 4 + chl) * 16 + cb];
            float gf = gsm[(1 * 4 + chl) * 16 + cb];
            float gg = gsm[(2 * 4 + chl) * 16 + cb];
            float go = gsm[(3 * 4 + chl) * 16 + cb];
            float iv = fsig(gi);
            float fv = fsig(gf);
            float gv = ftanh(gg);
            float ov = fsig(go);
            c_reg = fv * c_reg + iv * gv;
            float hv = ov * ftanh(c_reg);
            hout[ch * 16 + cb] = hv;
            ybase[((size_t)(cb * T_ + t)) * ystride + ch] = hv;
            if (t == T_ - 1) {
                hfin[cb * 512 + ch] = hv;
                cfin[cb * 512 + ch] = c_reg;
            }
        }
        grid_barrier();
    }
}

// ---------------- fused attention: energy + softmax + context -----------------
__global__ __launch_bounds__(256) void k_attn(
    const float* __restrict__ encf, const float* __restrict__ decf,
    const float* __restrict__ mem, const unsigned char* __restrict__ mask,
    const float* __restrict__ v, const float* __restrict__ vb,
    float* __restrict__ outcat) {
    __shared__ float df[8][512];
    __shared__ float vsh[512];
    __shared__ float row[512];
    __shared__ float en[8][128];
    const int b = blockIdx.x;
    const int t0 = blockIdx.y * 8;
    const int tid = threadIdx.x;
    const int w = tid >> 5, lane = tid & 31;

    for (int i = tid; i < 512; i += 256) vsh[i] = v[i];
    for (int i = tid; i < 8 * 512; i += 256) {
        int j = i >> 9, h = i & 511;
        df[j][h] = decf[((size_t)(b * T_ + t0 + j)) * 512 + h];
    }
    __syncthreads();
    const float vbv = vb[0];

    for (int s = 0; s < S_; s++) {
        for (int i = tid; i < 512; i += 256) row[i] = encf[((size_t)(b * S_ + s)) * 512 + i];
        __syncthreads();
        float e = 0.f;
#pragma unroll
        for (int i = 0; i < 16; i++) {
            int h = lane + 32 * i;
            e = fmaf(vsh[h], ftanh(row[h] + df[w][h]), e);
        }
#pragma unroll
        for (int off = 16; off; off >>= 1) e += __shfl_xor_sync(0xffffffffu, e, off);
        if (lane == 0) {
            e += vbv;
            if (mask[b * S_ + s]) e = -1e9f;
            en[w][s] = e;
        }
        __syncthreads();
    }

    {
        float vals[4];
        float m = -1e30f;
#pragma unroll
        for (int i = 0; i < 4; i++) { vals[i] = en[w][lane + 32 * i]; m = fmaxf(m, vals[i]); }
#pragma unroll
        for (int off = 16; off; off >>= 1) m = fmaxf(m, __shfl_xor_sync(0xffffffffu, m, off));
        float ssum = 0.f;
#pragma unroll
        for (int i = 0; i < 4; i++) { vals[i] = __expf(vals[i] - m); ssum += vals[i]; }
#pragma unroll
        for (int off = 16; off; off >>= 1) ssum += __shfl_xor_sync(0xffffffffu, ssum, off);
        float inv = 1.f / ssum;
#pragma unroll
        for (int i = 0; i < 4; i++) en[w][lane + 32 * i] = vals[i] * inv;
    }
    __syncthreads();

    float c0[8], c1[8];
#pragma unroll
    for (int j = 0; j < 8; j++) { c0[j] = 0.f; c1[j] = 0.f; }
    for (int s = 0; s < S_; s++) {
        for (int i = tid; i < 512; i += 256) row[i] = mem[((size_t)(b * S_ + s)) * 512 + i];
        __syncthreads();
        float m0 = row[tid], m1 = row[tid + 256];
#pragma unroll
        for (int j = 0; j < 8; j++) {
            float a = en[j][s];
            c0[j] = fmaf(a, m0, c0[j]);
            c1[j] = fmaf(a, m1, c1[j]);
        }
        __syncthreads();
    }
#pragma unroll
    for (int j = 0; j < 8; j++) {
        size_t r = ((size_t)(b * T_ + t0 + j)) * 1024 + 512;
        outcat[r + tid] = c0[j];
        outcat[r + tid + 256] = c1[j];
    }
}

// ---------------- launch -------------------------------------------------------
extern "C" void kernel_launch(void* const* d_in, const int* in_sizes, int n_in,
                              void* d_out, int out_size) {
    (void)in_sizes; (void)n_in; (void)out_size;
    const int*   tgt  = (const int*)d_in[0];
    const float* mem  = (const float*)d_in[1];
    const unsigned char* mask = (const unsigned char*)d_in[2];
    const float* emb  = (const float*)d_in[3];
    const float* Wih0 = (const float*)d_in[4];
    const float* Whh0 = (const float*)d_in[5];
    const float* bih0 = (const float*)d_in[6];
    const float* bhh0 = (const float*)d_in[7];
    const float* Wih1 = (const float*)d_in[8];
    const float* Whh1 = (const float*)d_in[9];
    const float* bih1 = (const float*)d_in[10];
    const float* bhh1 = (const float*)d_in[11];
    const float* Wh   = (const float*)d_in[12];
    const float* bh   = (const float*)d_in[13];
    const float* Ws   = (const float*)d_in[14];
    const float* bs   = (const float*)d_in[15];
    const float* v    = (const float*)d_in[16];
    const float* vb   = (const float*)d_in[17];
    const float* Wout = (const float*)d_in[18];
    const float* bout = (const float*)d_in[19];

    float* out = (float*)d_out;
    float* logits = out;
    float* hn = out + (size_t)B_ * T_ * V_;
    float* cn = hn + 2 * B_ * H_;

    float *px, *pgates, *py1, *pcat, *pencf, *pdecf, *pench, *ph0, *ph1;
    cudaGetSymbolAddress((void**)&px, g_x);
    cudaGetSymbolAddress((void**)&pgates, g_gates);
    cudaGetSymbolAddress((void**)&py1, g_y1);
    cudaGetSymbolAddress((void**)&pcat, g_cat);
    cudaGetSymbolAddress((void**)&pencf, g_encf);
    cudaGetSymbolAddress((void**)&pdecf, g_decf);
    cudaGetSymbolAddress((void**)&pench, g_ench_t);
    cudaGetSymbolAddress((void**)&ph0, g_h0);
    cudaGetSymbolAddress((void**)&ph1, g_h1);

    cudaFuncSetAttribute(k_lstm, cudaFuncAttributeMaxDynamicSharedMemorySize, LSTM_SMEM);

    // 1. embedding + enc_hidden (transposed)
    k_embed<<<2048, 128>>>(tgt, emb, px);
    k_mean<<<B_, 512>>>(mem, pench);

    // 2. layer0 input gates (tf32 mma), layer0 recurrence
    gemm_tf32<<<dim3(16, 16), 256>>>(px, 512, Wih0, 512, 512, bih0, bhh0, pgates, 2048);
    k_lstm<<<LSTM_BLOCKS, LSTM_THREADS, LSTM_SMEM>>>(pgates, Whh0, pench, py1, 512,
                                                     hn, cn, ph0, ph1);

    // 3. layer1 input gates, layer1 recurrence (y2 -> first half of g_cat)
    gemm_tf32<<<dim3(16, 16), 256>>>(py1, 512, Wih1, 512, 512, bih1, bhh1, pgates, 2048);
    k_lstm<<<LSTM_BLOCKS, LSTM_THREADS, LSTM_SMEM>>>(pgates, Whh1, pench, pcat, 1024,
                                                     hn + B_ * H_, cn + B_ * H_, ph0, ph1);

    // 4. attention features
    gemm_tf32<<<dim3(4, 16), 256>>>(mem, 512, Wh, 512, 512, bh, nullptr, pencf, 512);
    gemm_tf32<<<dim3(4, 16), 256>>>(pcat, 1024, Ws, 512, 512, bs, nullptr, pdecf, 512);

    // 5. fused energy/softmax/context -> second half of g_cat
    k_attn<<<dim3(B_, T_ / 8), 256>>>(pencf, pdecf, mem, mask, v, vb, pcat);

    // 6. output projection (tf32 mma)
    gemm_tf32<<<dim3(32, 16), 256>>>(pcat, 1024, Wout, 1024, 1024, bout, nullptr, logits, 4096);
}